// round 3
// baseline (speedup 1.0000x reference)
#include <cuda_runtime.h>
#include <cstdint>

// Problem constants
#define Bn 8
#define Cn 256
#define Hn 96
#define Wn 128
#define Dd 4
#define NS 9      // 2*D+1
#define Qn 81     // NS*NS
#define HW (Hn*Wn)

// Tiling
#define TY 2                  // y rows per block
#define RX 8                  // x pixels per thread
#define XG (Wn/RX)            // 16 x-groups
#define NTHREADS (TY*XG*NS)   // 288
#define CC 16                 // channels per smem chunk
#define NCHUNK (Cn/CC)        // 16
#define FBW (Wn + 2*Dd)       // 136
#define FBH (TY + 2*Dd)       // 10
#define VW (RX + 2*Dd)        // 16 window floats per thread

#define FA_FLOATS (CC*TY*Wn)          // 4096
#define FB_FLOATS (CC*FBH*FBW)        // 21760
#define STAGE_FLOATS (FA_FLOATS + FB_FLOATS)   // 25856
#define SMEM_BYTES (2*STAGE_FLOATS*4)          // 206848

#define FB_SLOTS (FBH*(FBW/4))        // 340 float4 slots per channel

typedef unsigned long long ull;

// Per-pixel inverse norms (scratch)
__device__ float g_inva[Bn*HW];
__device__ float g_invb[Bn*HW];

// ---------------------------------------------------------------------------
__device__ __forceinline__ ull pk(float lo, float hi) {
    ull r;
    asm("mov.b64 %0, {%1, %2};" : "=l"(r) : "f"(lo), "f"(hi));
    return r;
}
__device__ __forceinline__ void upk(float& lo, float& hi, ull p) {
    asm("mov.b64 {%0, %1}, %2;" : "=f"(lo), "=f"(hi) : "l"(p));
}
__device__ __forceinline__ void fma2(ull& d, ull a, ull b) {
    asm("fma.rn.f32x2 %0, %1, %2, %0;" : "+l"(d) : "l"(a), "l"(b));
}
__device__ __forceinline__ void cp16(uint32_t saddr, const float* g, int nbytes) {
    asm volatile("cp.async.cg.shared.global [%0], [%1], 16, %2;"
                 :: "r"(saddr), "l"(g), "r"(nbytes));
}

// ---------------------------------------------------------------------------
// Pass 1: per-pixel inverse L2 norms (HBM-bound, ~26us). 4 pixels per thread.
// ---------------------------------------------------------------------------
__global__ void norm_kernel(const float* __restrict__ fa,
                            const float* __restrict__ fb) {
    int p4 = blockIdx.x * blockDim.x + threadIdx.x;   // float4 index, 0..3071
    int b  = blockIdx.y;
    const float4* pa = (const float4*)(fa + (size_t)b * Cn * HW) + p4;
    const float4* pb = (const float4*)(fb + (size_t)b * Cn * HW) + p4;
    float4 sa = make_float4(0.f, 0.f, 0.f, 0.f);
    float4 sb = make_float4(0.f, 0.f, 0.f, 0.f);
#pragma unroll 4
    for (int c = 0; c < Cn; c++) {
        float4 va = pa[(size_t)c * (HW / 4)];
        float4 vb = pb[(size_t)c * (HW / 4)];
        sa.x = fmaf(va.x, va.x, sa.x); sa.y = fmaf(va.y, va.y, sa.y);
        sa.z = fmaf(va.z, va.z, sa.z); sa.w = fmaf(va.w, va.w, sa.w);
        sb.x = fmaf(vb.x, vb.x, sb.x); sb.y = fmaf(vb.y, vb.y, sb.y);
        sb.z = fmaf(vb.z, vb.z, sb.z); sb.w = fmaf(vb.w, vb.w, sb.w);
    }
    float4 oa, ob;
    oa.x = 1.0f / fmaxf(sqrtf(sa.x), 1e-12f);
    oa.y = 1.0f / fmaxf(sqrtf(sa.y), 1e-12f);
    oa.z = 1.0f / fmaxf(sqrtf(sa.z), 1e-12f);
    oa.w = 1.0f / fmaxf(sqrtf(sa.w), 1e-12f);
    ob.x = 1.0f / fmaxf(sqrtf(sb.x), 1e-12f);
    ob.y = 1.0f / fmaxf(sqrtf(sb.y), 1e-12f);
    ob.z = 1.0f / fmaxf(sqrtf(sb.z), 1e-12f);
    ob.w = 1.0f / fmaxf(sqrtf(sb.w), 1e-12f);
    ((float4*)g_inva)[b * (HW / 4) + p4] = oa;
    ((float4*)g_invb)[b * (HW / 4) + p4] = ob;
}

// ---------------------------------------------------------------------------
// Pass 2: correlation. Thread = (yl, 8 x-pixels, one dy) -> 72 acc (36 f32x2).
// Per channel: 2 LDS.128 fa + 4 LDS.128 fb + 36 FFMA2 (+~7 pack MOVs on alu).
// 2-stage cp.async pipeline, CC=16.
// ---------------------------------------------------------------------------
__global__ void __launch_bounds__(NTHREADS, 1)
corr_kernel(const float* __restrict__ fa,
            const float* __restrict__ fb,
            float* __restrict__ out) {
    extern __shared__ float smem[];

    const int b   = blockIdx.y;
    const int y0  = blockIdx.x * TY;
    const int tid = threadIdx.x;

    const int dy = tid / (TY * XG);          // 0..8 (uniform per warp)
    const int r  = tid % (TY * XG);
    const int yl = r / XG;                   // 0..1
    const int xg = r % XG;                   // 0..15
    const int x0 = xg * RX;

    const size_t baseA = (size_t)b * Cn * HW;

    // ---- loader roles (hoisted) ----
    // fa: 64 float4 slots per channel
    const bool fa_role = (tid < TY * (Wn / 4));
    int fa_gofs = 0, fa_sofs = 0;
    if (fa_role) {
        int yy  = tid / (Wn / 4);
        int xx4 = tid % (Wn / 4);
        fa_gofs = (y0 + yy) * Wn + xx4 * 4;
        fa_sofs = yy * Wn + xx4 * 4;
    }
    // fb: 340 slots per channel; thread covers slot tid and slot tid+288
    int fb_gofs[2] = {0, 0}, fb_sofs[2] = {0, 0}, fb_bytes[2] = {0, 0};
    bool fb_has[2] = {true, (tid + NTHREADS) < FB_SLOTS};
#pragma unroll
    for (int s = 0; s < 2; s++) {
        int slot = tid + s * NTHREADS;
        if (slot < FB_SLOTS) {
            int hr = slot / (FBW / 4);
            int k  = slot % (FBW / 4);
            int yy = y0 - Dd + hr;
            bool valid = (yy >= 0) && (yy < Hn) && (k >= 1) && (k <= Wn / 4);
            fb_bytes[s] = valid ? 16 : 0;
            int yyc = min(max(yy, 0), Hn - 1);
            int kc  = min(max(k, 1), Wn / 4);
            fb_gofs[s] = yyc * Wn + (kc * 4 - 4);
            fb_sofs[s] = hr * FBW + k * 4;
        }
    }

    const uint32_t smem_u = (uint32_t)__cvta_generic_to_shared(smem);

    auto prefetch = [&](int c0, int st) {
        const uint32_t sbase = smem_u + (uint32_t)(st * STAGE_FLOATS * 4);
        const float* ga = fa + baseA + (size_t)c0 * HW;
        const float* gb = fb + baseA + (size_t)c0 * HW;
#pragma unroll
        for (int cc = 0; cc < CC; cc++) {
            if (fa_role)
                cp16(sbase + (uint32_t)((cc * (TY * Wn) + fa_sofs) * 4),
                     ga + (size_t)cc * HW + fa_gofs, 16);
            cp16(sbase + (uint32_t)((FA_FLOATS + cc * (FBH * FBW) + fb_sofs[0]) * 4),
                 gb + (size_t)cc * HW + fb_gofs[0], fb_bytes[0]);
            if (fb_has[1])
                cp16(sbase + (uint32_t)((FA_FLOATS + cc * (FBH * FBW) + fb_sofs[1]) * 4),
                     gb + (size_t)cc * HW + fb_gofs[1], fb_bytes[1]);
        }
    };

    ull acc2[NS * 4];   // 9 dx x 4 pixel-pairs
#pragma unroll
    for (int i = 0; i < NS * 4; i++) acc2[i] = 0ull;

    const int ofsA = yl * Wn + x0;
    const int ofsB = (yl + dy) * FBW + x0;

    // ---- pipeline prologue ----
    prefetch(0, 0);
    asm volatile("cp.async.commit_group;");

    int st = 0;
    for (int ch = 0; ch < NCHUNK; ch++) {
        asm volatile("cp.async.wait_group 0;");
        __syncthreads();
        if (ch + 1 < NCHUNK) prefetch((ch + 1) * CC, st ^ 1);
        asm volatile("cp.async.commit_group;");

        const float* s_fa = smem + st * STAGE_FLOATS;
        const float* s_fb = s_fa + FA_FLOATS;
#pragma unroll 2
        for (int cc = 0; cc < CC; cc++) {
            const float* fap = s_fa + cc * (TY * Wn) + ofsA;
            const float* fbp = s_fb + cc * (FBH * FBW) + ofsB;
            float4 A0 = *(const float4*)(fap);
            float4 A1 = *(const float4*)(fap + 4);
            float4 V0 = *(const float4*)(fbp);
            float4 V1 = *(const float4*)(fbp + 4);
            float4 V2 = *(const float4*)(fbp + 8);
            float4 V3 = *(const float4*)(fbp + 12);

            ull a2[4] = {pk(A0.x, A0.y), pk(A0.z, A0.w),
                         pk(A1.x, A1.y), pk(A1.z, A1.w)};
            float v[VW] = {V0.x, V0.y, V0.z, V0.w, V1.x, V1.y, V1.z, V1.w,
                           V2.x, V2.y, V2.z, V2.w, V3.x, V3.y, V3.z, V3.w};
            ull p[VW - 1];
#pragma unroll
            for (int k = 0; k < VW - 1; k++) p[k] = pk(v[k], v[k + 1]);

#pragma unroll
            for (int dx = 0; dx < NS; dx++)
#pragma unroll
                for (int j = 0; j < 4; j++)
                    fma2(acc2[dx * 4 + j], a2[j], p[dx + 2 * j]);
        }
        st ^= 1;
    }

    // ---- epilogue: scale by inverse norms, write 2x float4 per dx ----
    const int y = y0 + yl;
    float ia[RX];
#pragma unroll
    for (int i = 0; i < RX; i++) ia[i] = g_inva[b * HW + y * Wn + x0 + i];

    const int sy = y + dy - Dd;
    const bool rowok = (unsigned)sy < (unsigned)Hn;
    float ib[VW];
#pragma unroll
    for (int k = 0; k < VW; k++) {
        int sx = x0 + k - Dd;
        ib[k] = (rowok && (unsigned)sx < (unsigned)Wn)
                    ? g_invb[b * HW + sy * Wn + sx] : 0.f;
    }

#pragma unroll
    for (int dx = 0; dx < NS; dx++) {
        float o[RX];
#pragma unroll
        for (int j = 0; j < 4; j++) {
            float lo, hi;
            upk(lo, hi, acc2[dx * 4 + j]);
            o[2 * j + 0] = lo * ia[2 * j + 0] * ib[dx + 2 * j + 0];
            o[2 * j + 1] = hi * ia[2 * j + 1] * ib[dx + 2 * j + 1];
        }
        const int q = dy * NS + dx;
        float* op = out + ((size_t)(b * Qn + q) * Hn + y) * Wn + x0;
        *(float4*)(op)     = make_float4(o[0], o[1], o[2], o[3]);
        *(float4*)(op + 4) = make_float4(o[4], o[5], o[6], o[7]);
    }
}

// ---------------------------------------------------------------------------
extern "C" void kernel_launch(void* const* d_in, const int* in_sizes, int n_in,
                              void* d_out, int out_size) {
    const float* fa = (const float*)d_in[0];
    const float* fb = (const float*)d_in[1];
    float* out = (float*)d_out;

    norm_kernel<<<dim3(HW / 4 / 256, Bn), 256>>>(fa, fb);

    cudaFuncSetAttribute(corr_kernel,
                         cudaFuncAttributeMaxDynamicSharedMemorySize,
                         SMEM_BYTES);
    corr_kernel<<<dim3(Hn / TY, Bn), NTHREADS, SMEM_BYTES>>>(fa, fb, out);
}

// round 4
// speedup vs baseline: 1.5218x; 1.5218x over previous
#include <cuda_runtime.h>
#include <cstdint>

// Problem constants
#define Bn 8
#define Cn 256
#define Hn 96
#define Wn 128
#define Dd 4
#define NS 9      // 2*D+1
#define Qn 81     // NS*NS
#define HW (Hn*Wn)

// Tiling
#define TY 2                  // y rows per block
#define RX 4                  // x pixels per thread
#define XG (Wn/RX)            // 32 x-groups
#define NTHREADS (TY*XG*NS)   // 576
#define CC 8                  // channels per smem chunk
#define NCHUNK (Cn/CC)        // 32
#define NSTAGES 3
#define FBW (Wn + 2*Dd)       // 136
#define FBH (TY + 2*Dd)       // 10
#define VW (RX + 2*Dd)        // 12 window floats per thread

#define FA_FLOATS (CC*TY*Wn)          // 2048
#define FB_FLOATS (CC*FBH*FBW)        // 10880
#define STAGE_FLOATS (FA_FLOATS + FB_FLOATS)   // 12928
#define SMEM_BYTES (NSTAGES*STAGE_FLOATS*4)    // 155136

#define FA_SLOTS (CC*TY*(Wn/4))       // 512
#define FB_SLOTS (CC*FBH*(FBW/4))     // 2720
#define TOT_SLOTS (FA_SLOTS+FB_SLOTS) // 3232
#define MAXSL 6                       // ceil(3232/576)

typedef unsigned long long ull;

// Per-pixel inverse norms (scratch)
__device__ float g_inva[Bn*HW];
__device__ float g_invb[Bn*HW];

// ---------------------------------------------------------------------------
__device__ __forceinline__ ull pk(float lo, float hi) {
    ull r;
    asm("mov.b64 %0, {%1, %2};" : "=l"(r) : "f"(lo), "f"(hi));
    return r;
}
__device__ __forceinline__ void upk(float& lo, float& hi, ull p) {
    asm("mov.b64 {%0, %1}, %2;" : "=f"(lo), "=f"(hi) : "l"(p));
}
__device__ __forceinline__ void fma2(ull& d, ull a, ull b) {
    asm("fma.rn.f32x2 %0, %1, %2, %0;" : "+l"(d) : "l"(a), "l"(b));
}
__device__ __forceinline__ void cp16(uint32_t saddr, const float* g, int nbytes) {
    asm volatile("cp.async.cg.shared.global [%0], [%1], 16, %2;"
                 :: "r"(saddr), "l"(g), "r"(nbytes));
}

// ---------------------------------------------------------------------------
// Pass 1: per-pixel inverse L2 norms (round-2 scalar version; ~33us)
// ---------------------------------------------------------------------------
__global__ void norm_kernel(const float* __restrict__ fa,
                            const float* __restrict__ fb) {
    int pix = blockIdx.x * blockDim.x + threadIdx.x;
    int b   = blockIdx.y;
    const float* pa = fa + (size_t)b * Cn * HW + pix;
    const float* pb = fb + (size_t)b * Cn * HW + pix;
    float sa = 0.f, sb = 0.f;
#pragma unroll 8
    for (int c = 0; c < Cn; c++) {
        float va = pa[(size_t)c * HW];
        float vb = pb[(size_t)c * HW];
        sa = fmaf(va, va, sa);
        sb = fmaf(vb, vb, sb);
    }
    g_inva[b * HW + pix] = 1.0f / fmaxf(sqrtf(sa), 1e-12f);
    g_invb[b * HW + pix] = 1.0f / fmaxf(sqrtf(sb), 1e-12f);
}

// ---------------------------------------------------------------------------
// Pass 2: correlation. 576 threads: (yl, 4 x-pixels, one dy).
// f32x2 accumulators: 18 FFMA2 + 4 LDS.128 per channel-thread.
// 3-stage cp.async pipeline (CC=8), balanced loader slots.
// ---------------------------------------------------------------------------
__global__ void __launch_bounds__(NTHREADS, 1)
corr_kernel(const float* __restrict__ fa,
            const float* __restrict__ fb,
            float* __restrict__ out) {
    extern __shared__ float smem[];

    const int b   = blockIdx.y;
    const int y0  = blockIdx.x * TY;
    const int tid = threadIdx.x;

    const int dy = tid / (TY * XG);          // 0..8 (uniform per warp)
    const int r  = tid % (TY * XG);
    const int yl = r / XG;                   // 0..1
    const int xg = r % XG;                   // 0..31
    const int x0 = xg * RX;

    const size_t baseA = (size_t)b * Cn * HW;

    // ---- balanced loader slot descriptors (hoisted) ----
    int  ld_g[MAXSL], ld_s[MAXSL], ld_nb[MAXSL];
    bool ld_live[MAXSL], ld_isA[MAXSL];
#pragma unroll
    for (int si = 0; si < MAXSL; si++) {
        int slot = tid + si * NTHREADS;
        ld_live[si] = (slot < TOT_SLOTS);
        ld_isA[si] = false; ld_g[si] = 0; ld_s[si] = 0; ld_nb[si] = 0;
        if (ld_live[si]) {
            if (slot < FA_SLOTS) {
                int cc = slot / (TY * (Wn / 4));
                int rr = slot % (TY * (Wn / 4));
                int yy = rr / (Wn / 4);
                int x4 = rr % (Wn / 4);
                ld_isA[si] = true;
                ld_nb[si]  = 16;
                ld_g[si]   = cc * HW + (y0 + yy) * Wn + x4 * 4;
                ld_s[si]   = cc * (TY * Wn) + yy * Wn + x4 * 4;
            } else {
                int t  = slot - FA_SLOTS;
                int cc = t / (FBH * (FBW / 4));
                int u  = t % (FBH * (FBW / 4));
                int hr = u / (FBW / 4);
                int k  = u % (FBW / 4);
                int yy = y0 - Dd + hr;
                bool valid = (yy >= 0) && (yy < Hn) && (k >= 1) && (k <= Wn / 4);
                ld_nb[si] = valid ? 16 : 0;          // zfill for halo/OOB
                int yyc = min(max(yy, 0), Hn - 1);
                int kc  = min(max(k, 1), Wn / 4);
                ld_g[si] = cc * HW + yyc * Wn + kc * 4 - 4;
                ld_s[si] = FA_FLOATS + cc * (FBH * FBW) + hr * FBW + k * 4;
            }
        }
    }

    const uint32_t smem_u = (uint32_t)__cvta_generic_to_shared(smem);

    auto prefetch = [&](int c0, int st) {
        const uint32_t sbase = smem_u + (uint32_t)(st * STAGE_FLOATS * 4);
        const float* ga = fa + baseA + (size_t)c0 * HW;
        const float* gb = fb + baseA + (size_t)c0 * HW;
#pragma unroll
        for (int si = 0; si < MAXSL; si++) {
            if (ld_live[si]) {
                const float* src = (ld_isA[si] ? ga : gb) + ld_g[si];
                cp16(sbase + (uint32_t)(ld_s[si] * 4), src, ld_nb[si]);
            }
        }
    };

    ull acc2[NS * 2];   // 9 dx x 2 pixel-pairs
#pragma unroll
    for (int i = 0; i < NS * 2; i++) acc2[i] = 0ull;

    const int ofsA = yl * Wn + x0;
    const int ofsB = (yl + dy) * FBW + x0;

    // ---- pipeline prologue: 2 chunks in flight ----
    prefetch(0, 0);
    asm volatile("cp.async.commit_group;");
    prefetch(CC, 1);
    asm volatile("cp.async.commit_group;");

    int cs = 0;  // compute stage
    for (int ch = 0; ch < NCHUNK; ch++) {
        asm volatile("cp.async.wait_group 1;");   // chunk ch landed
        __syncthreads();                          // stage (ch+2)%3 reusable
        int ps = cs + 2; if (ps >= NSTAGES) ps -= NSTAGES;
        if (ch + 2 < NCHUNK) prefetch((ch + 2) * CC, ps);
        asm volatile("cp.async.commit_group;");   // unconditional (group count)

        const float* s_fa = smem + cs * STAGE_FLOATS;
        const float* s_fb = s_fa + FA_FLOATS;
#pragma unroll
        for (int cc = 0; cc < CC; cc++) {
            const float* fap = s_fa + cc * (TY * Wn) + ofsA;
            const float* fbp = s_fb + cc * (FBH * FBW) + ofsB;
            float4 A  = *(const float4*)(fap);
            float4 V0 = *(const float4*)(fbp);
            float4 V1 = *(const float4*)(fbp + 4);
            float4 V2 = *(const float4*)(fbp + 8);

            ull a2[2] = {pk(A.x, A.y), pk(A.z, A.w)};
            float v[VW] = {V0.x, V0.y, V0.z, V0.w, V1.x, V1.y, V1.z, V1.w,
                           V2.x, V2.y, V2.z, V2.w};
            ull p[VW - 1];
#pragma unroll
            for (int k = 0; k < VW - 1; k++) p[k] = pk(v[k], v[k + 1]);

#pragma unroll
            for (int dx = 0; dx < NS; dx++) {
                fma2(acc2[dx * 2 + 0], a2[0], p[dx + 0]);
                fma2(acc2[dx * 2 + 1], a2[1], p[dx + 2]);
            }
        }
        cs++; if (cs >= NSTAGES) cs = 0;
    }

    // ---- epilogue: scale by inverse norms, write float4 per dx ----
    const int y = y0 + yl;
    float ia[RX];
#pragma unroll
    for (int i = 0; i < RX; i++) ia[i] = g_inva[b * HW + y * Wn + x0 + i];

    const int sy = y + dy - Dd;
    const bool rowok = (unsigned)sy < (unsigned)Hn;
    float ib[VW];
#pragma unroll
    for (int k = 0; k < VW; k++) {
        int sx = x0 + k - Dd;
        ib[k] = (rowok && (unsigned)sx < (unsigned)Wn)
                    ? g_invb[b * HW + sy * Wn + sx] : 0.f;
        // raw acc is exactly 0 for OOB (zfill halo), so ib=0 is safe
    }

#pragma unroll
    for (int dx = 0; dx < NS; dx++) {
        float o[RX];
        float lo, hi;
        upk(lo, hi, acc2[dx * 2 + 0]);
        o[0] = lo * ia[0] * ib[dx + 0];
        o[1] = hi * ia[1] * ib[dx + 1];
        upk(lo, hi, acc2[dx * 2 + 1]);
        o[2] = lo * ia[2] * ib[dx + 2];
        o[3] = hi * ia[3] * ib[dx + 3];
        const int q = dy * NS + dx;
        *(float4*)(out + ((size_t)(b * Qn + q) * Hn + y) * Wn + x0) =
            make_float4(o[0], o[1], o[2], o[3]);
    }
}

// ---------------------------------------------------------------------------
extern "C" void kernel_launch(void* const* d_in, const int* in_sizes, int n_in,
                              void* d_out, int out_size) {
    const float* fa = (const float*)d_in[0];
    const float* fb = (const float*)d_in[1];
    float* out = (float*)d_out;

    norm_kernel<<<dim3(HW / 256, Bn), 256>>>(fa, fb);

    cudaFuncSetAttribute(corr_kernel,
                         cudaFuncAttributeMaxDynamicSharedMemorySize,
                         SMEM_BYTES);
    corr_kernel<<<dim3(Hn / TY, Bn), NTHREADS, SMEM_BYTES>>>(fa, fb, out);
}